// round 4
// baseline (speedup 1.0000x reference)
#include <cuda_runtime.h>

#define HIDDEN 1024
#define HEADS 16
#define HD 64
#define RANK 16
#define BSZ 4
#define SEQ 2048
#define BH (BSZ*HEADS)          // 64
#define NPROJ 3
#define LORA_SCALE (1.0f/16.0f)
#define SM_SCALE 0.125f          // 1/sqrt(64)

// k-permutation within 8-groups: pos(c) = ((c&3)<<1)|((c>>2)&1)  -> pairs (t,t+4) adjacent
#define PERM8(c) ( ((c) & ~7) | ((((c)&3)<<1) | (((c)>>2)&1)) )

// Scratch
__device__ float g_Weff[(size_t)NPROJ*HIDDEN*HIDDEN];   // tf32 bits, k-permuted
__device__ float g_Xtf [(size_t)BSZ*SEQ*HIDDEN];        // tf32 bits, k-permuted
__device__ float g_QKV [(size_t)NPROJ*BH*SEQ*HD];       // Q,K: [bh][s][d'] d-permuted; V: [bh][d][s'] s-permuted

// ---------------------------------------------------------------------------
__device__ __forceinline__ unsigned f2tf(float f) {
    unsigned u;
    asm("cvt.rna.tf32.f32 %0, %1;" : "=r"(u) : "f"(f));
    return u;
}
__device__ __forceinline__ float f2tf_f(float f) { return __uint_as_float(f2tf(f)); }

__device__ __forceinline__ void mma_tf32(float c[4], const unsigned a[4], unsigned b0, unsigned b1) {
    asm volatile(
        "mma.sync.aligned.m16n8k8.row.col.f32.tf32.tf32.f32 "
        "{%0,%1,%2,%3},{%4,%5,%6,%7},{%8,%9},{%0,%1,%2,%3};"
        : "+f"(c[0]), "+f"(c[1]), "+f"(c[2]), "+f"(c[3])
        : "r"(a[0]), "r"(a[1]), "r"(a[2]), "r"(a[3]), "r"(b0), "r"(b1));
}
__device__ __forceinline__ void cpa16(float* dst, const float* src) {
    unsigned a = (unsigned)__cvta_generic_to_shared(dst);
    asm volatile("cp.async.cg.shared.global [%0], [%1], 16;" :: "r"(a), "l"(src));
}
#define CP_COMMIT asm volatile("cp.async.commit_group;")
#define CP_WAIT0  asm volatile("cp.async.wait_group 0;")
#define CP_WAIT1  asm volatile("cp.async.wait_group 1;")

// ---------------------------------------------------------------------------
// Kernel 1a: W_eff = tf32(W + (1/16) B A), stored k-permuted
// ---------------------------------------------------------------------------
__global__ void weff_kernel(const float* __restrict__ Wq, const float* __restrict__ Aq, const float* __restrict__ Bq,
                            const float* __restrict__ Wk, const float* __restrict__ Ak, const float* __restrict__ Bk,
                            const float* __restrict__ Wv, const float* __restrict__ Av, const float* __restrict__ Bv) {
    int idx = blockIdx.x * blockDim.x + threadIdx.x;
    if (idx >= NPROJ*HIDDEN*HIDDEN) return;
    int p  = idx >> 20;
    int nk = idx & ((1 << 20) - 1);
    int n  = nk >> 10;
    int k  = nk & 1023;
    const float* W = (p == 0) ? Wq : ((p == 1) ? Wk : Wv);
    const float* A = (p == 0) ? Aq : ((p == 1) ? Ak : Av);
    const float* B = (p == 0) ? Bq : ((p == 1) ? Bk : Bv);
    float acc = 0.f;
#pragma unroll
    for (int r = 0; r < RANK; r++) acc += B[n*RANK + r] * A[r*HIDDEN + k];
    g_Weff[((size_t)p << 20) + ((size_t)n << 10) + PERM8(k)] = f2tf_f(W[nk] + LORA_SCALE * acc);
}

// ---------------------------------------------------------------------------
// Kernel 1b: X -> tf32, k-permuted
// ---------------------------------------------------------------------------
__global__ void xtf_kernel(const float* __restrict__ X) {
    int i  = blockIdx.x * blockDim.x + threadIdx.x;   // float4 index
    int c4 = (i << 2) & 1023;
    size_t row = ((size_t)(i << 2)) & ~1023ull;
    float4 v = ((const float4*)X)[i];
    float* dst = g_Xtf + row;
    dst[PERM8(c4+0)] = f2tf_f(v.x);
    dst[PERM8(c4+1)] = f2tf_f(v.y);
    dst[PERM8(c4+2)] = f2tf_f(v.z);
    dst[PERM8(c4+3)] = f2tf_f(v.w);
}

// ---------------------------------------------------------------------------
// Kernel 2: QKV GEMM, mma tf32, cp.async 2-stage, LDS.64 fragments.
// ---------------------------------------------------------------------------
#define GST 40
#define SAB (128*GST)

__global__ __launch_bounds__(256) void qkv_gemm_tf32(const float* __restrict__ bq,
                                                     const float* __restrict__ bk,
                                                     const float* __restrict__ bv) {
    extern __shared__ __align__(16) float gsm[];
    int tid  = threadIdx.x;
    int lane = tid & 31;
    int wid  = tid >> 5;
    int wm   = wid & 3;
    int wn   = wid >> 2;
    int g    = lane >> 2;
    int tig  = lane & 3;
    int m0 = blockIdx.y * 128;
    int n0 = blockIdx.x * 128;

    float acc[2][8][4];
#pragma unroll
    for (int mt = 0; mt < 2; mt++)
#pragma unroll
        for (int nt = 0; nt < 8; nt++)
#pragma unroll
            for (int i = 0; i < 4; i++) acc[mt][nt][i] = 0.f;

    int frow = tid >> 3;
    int fc4  = (tid & 7) << 2;

#define ISSUE(slab, buf) do {                                                     \
        float* sA_ = gsm + (buf)*2*SAB;                                           \
        float* sB_ = sA_ + SAB;                                                   \
        int kc_ = (slab)*32;                                                      \
        _Pragma("unroll")                                                         \
        for (int it = 0; it < 4; it++) {                                          \
            int row = frow + it*32;                                               \
            cpa16(sA_ + row*GST + fc4, g_Xtf  + (size_t)(m0+row)*HIDDEN + kc_ + fc4); \
            cpa16(sB_ + row*GST + fc4, g_Weff + (size_t)(n0+row)*HIDDEN + kc_ + fc4); \
        }                                                                         \
        CP_COMMIT;                                                                \
    } while (0)

    ISSUE(0, 0);

    for (int s = 0; s < HIDDEN/32; s++) {
        if (s + 1 < HIDDEN/32) { ISSUE(s+1, (s+1)&1); CP_WAIT1; }
        else                   { CP_WAIT0; }
        __syncthreads();

        const unsigned* uA = (const unsigned*)(gsm + (s&1)*2*SAB);
        const unsigned* uB = uA + SAB;
#pragma unroll
        for (int ks = 0; ks < 4; ks++) {
            int k0 = ks * 8;
            unsigned a[2][4], b[8][2];
#pragma unroll
            for (int mt = 0; mt < 2; mt++) {
                int rb = wm*32 + mt*16;
                uint2 lo = *(const uint2*)&uA[(rb+g  )*GST + k0 + 2*tig];
                uint2 hi = *(const uint2*)&uA[(rb+g+8)*GST + k0 + 2*tig];
                a[mt][0] = lo.x; a[mt][2] = lo.y;
                a[mt][1] = hi.x; a[mt][3] = hi.y;
            }
#pragma unroll
            for (int nt = 0; nt < 8; nt++) {
                int cb = wn*64 + nt*8;
                uint2 bb = *(const uint2*)&uB[(cb+g)*GST + k0 + 2*tig];
                b[nt][0] = bb.x; b[nt][1] = bb.y;
            }
#pragma unroll
            for (int mt = 0; mt < 2; mt++)
#pragma unroll
                for (int nt = 0; nt < 8; nt++)
                    mma_tf32(acc[mt][nt], a[mt], b[nt][0], b[nt][1]);
        }
        __syncthreads();
    }

    // epilogue: bias + tf32 round; Q,K -> [bh][s][perm d]; V -> [bh][d][perm s]
#pragma unroll
    for (int mt = 0; mt < 2; mt++) {
#pragma unroll
        for (int half = 0; half < 2; half++) {
            int m  = m0 + wm*32 + mt*16 + g + half*8;
            int b  = m >> 11;
            int sq = m & 2047;
            int sqp = PERM8(sq);
#pragma unroll
            for (int nt = 0; nt < 8; nt++) {
                int n  = n0 + wn*64 + nt*8 + 2*tig;
                int p  = n >> 10;
                int hn = n & 1023;
                int h  = hn >> 6;
                int d  = n & 63;
                const float* bias = (p == 0) ? bq : ((p == 1) ? bk : bv);
                float v0 = f2tf_f(acc[mt][nt][half*2 + 0] + bias[hn]);
                float v1 = f2tf_f(acc[mt][nt][half*2 + 1] + bias[hn + 1]);
                int bh = b*HEADS + h;
                if (p < 2) {
                    float* dst = &g_QKV[(((size_t)p * BH + bh) * SEQ + sq) * HD];
                    dst[PERM8(d)]   = v0;
                    dst[PERM8(d+1)] = v1;
                } else {
                    float* dst = &g_QKV[(size_t)2*BH*SEQ*HD + ((size_t)bh * HD) * SEQ + sqp];
                    dst[(size_t)d    *SEQ] = v0;
                    dst[(size_t)(d+1)*SEQ] = v1;
                }
            }
        }
    }
}

// ---------------------------------------------------------------------------
// Kernel 3: flash attention, mma tf32, LDS.64 fragments, occ-forced.
// ---------------------------------------------------------------------------
#define SKS 72
#define SVT 72
#define SPS 72
#define SMEM_K_WORDS (64*SKS)
#define SMEM_V_WORDS (64*SVT)
#define SMEM_P_WORDS (64*SPS)
#define ATTN_SMEM ((SMEM_K_WORDS + SMEM_V_WORDS + SMEM_P_WORDS + 64) * 4)

__global__ __launch_bounds__(128, 4) void attn_tf32(const float* __restrict__ mask,
                                                    float* __restrict__ out) {
    extern __shared__ __align__(16) float asm_[];
    float* sK     = asm_;
    float* sVt    = sK  + SMEM_K_WORDS;          // [d][perm key]
    float* sPbase = sVt + SMEM_V_WORDS;
    float* sM     = sPbase + SMEM_P_WORDS;

    int bh = blockIdx.y;
    int b  = bh >> 4;
    int h  = bh & 15;
    int q0 = blockIdx.x * 64;
    int tid  = threadIdx.x;
    int w    = tid >> 5;
    int lane = tid & 31;
    int g    = lane >> 2;
    int tig  = lane & 3;

    // per-thread P scatter columns (key cols 2tig, 2tig+1 -> permuted pos)
    int pc0 = ((2*tig)   & 3)*2 + ((2*tig)   >> 2);
    int pc1 = ((2*tig+1) & 3)*2 + ((2*tig+1) >> 2);

    // ---- stage Q (64x64, d-permuted) into sP region ----
    {
        const float* Qg = g_QKV + ((size_t)bh * SEQ + q0) * HD;
#pragma unroll
        for (int it = 0; it < 8; it++) {
            int f   = tid + it * 128;
            int row = f >> 4;
            int c4  = (f & 15) << 2;
            cpa16(sPbase + row*SPS + c4, Qg + row*HD + c4);
        }
        CP_COMMIT; CP_WAIT0;
    }
    __syncthreads();

    unsigned qa[8][4];
    int qb = w * 16;
    {
        const unsigned* uQ = (const unsigned*)sPbase;
#pragma unroll
        for (int kt = 0; kt < 8; kt++) {
            uint2 lo = *(const uint2*)&uQ[(qb+g  )*SPS + kt*8 + 2*tig];
            uint2 hi = *(const uint2*)&uQ[(qb+g+8)*SPS + kt*8 + 2*tig];
            qa[kt][0] = lo.x; qa[kt][2] = lo.y;
            qa[kt][1] = hi.x; qa[kt][3] = hi.y;
        }
    }
    __syncthreads();

    unsigned* sPw = (unsigned*)(sPbase + w * 16 * SPS);

    float o[8][4];
#pragma unroll
    for (int nt = 0; nt < 8; nt++)
#pragma unroll
        for (int i = 0; i < 4; i++) o[nt][i] = 0.f;
    float mlo = -1e30f, mhi = -1e30f, llo = 0.f, lhi = 0.f;

    const float* maskb = mask + b * SEQ;
    const float* Kg0 = g_QKV + ((size_t)(BH + bh) * SEQ) * HD;
    const float* Vg0 = g_QKV + (size_t)2*BH*SEQ*HD + (size_t)bh * HD * SEQ;

    for (int kt0 = 0; kt0 < SEQ; kt0 += 64) {
        // ---- stage K [key][perm d], Vt [d][perm key], mask ----
#pragma unroll
        for (int it = 0; it < 8; it++) {
            int f   = tid + it * 128;
            int row = f >> 4;
            int c4  = (f & 15) << 2;
            cpa16(sK  + row*SKS + c4, Kg0 + (size_t)(kt0 + row)*HD + c4);
            cpa16(sVt + row*SVT + c4, Vg0 + (size_t)row*SEQ + kt0 + c4);
        }
        if (tid < 16) cpa16(sM + tid*4, maskb + kt0 + tid*4);
        CP_COMMIT; CP_WAIT0;
        __syncthreads();

        const unsigned* uK = (const unsigned*)sK;
        const unsigned* uV = (const unsigned*)sVt;

        // ---- S = Q K^T ----
        float s[8][4];
#pragma unroll
        for (int nt = 0; nt < 8; nt++) {
            s[nt][0] = s[nt][1] = s[nt][2] = s[nt][3] = 0.f;
#pragma unroll
            for (int kt = 0; kt < 8; kt++) {
                uint2 bb = *(const uint2*)&uK[(nt*8+g)*SKS + kt*8 + 2*tig];
                mma_tf32(s[nt], qa[kt], bb.x, bb.y);
            }
        }

        // ---- scale + mask + tile max ----
        float tml = -1e30f, tmh = -1e30f;
#pragma unroll
        for (int nt = 0; nt < 8; nt++) {
            int c = nt*8 + 2*tig;
            float m0v = sM[c], m1v = sM[c+1];
            s[nt][0] = s[nt][0] * SM_SCALE + m0v;
            s[nt][1] = s[nt][1] * SM_SCALE + m1v;
            s[nt][2] = s[nt][2] * SM_SCALE + m0v;
            s[nt][3] = s[nt][3] * SM_SCALE + m1v;
            tml = fmaxf(tml, fmaxf(s[nt][0], s[nt][1]));
            tmh = fmaxf(tmh, fmaxf(s[nt][2], s[nt][3]));
        }
        tml = fmaxf(tml, __shfl_xor_sync(0xffffffff, tml, 1));
        tml = fmaxf(tml, __shfl_xor_sync(0xffffffff, tml, 2));
        tmh = fmaxf(tmh, __shfl_xor_sync(0xffffffff, tmh, 1));
        tmh = fmaxf(tmh, __shfl_xor_sync(0xffffffff, tmh, 2));

        float mnl = fmaxf(mlo, tml), mnh = fmaxf(mhi, tmh);
        float cl = __expf(mlo - mnl), ch = __expf(mhi - mnh);
        llo *= cl; lhi *= ch;
        mlo = mnl; mhi = mnh;
#pragma unroll
        for (int nt = 0; nt < 8; nt++) {
            o[nt][0] *= cl; o[nt][1] *= cl;
            o[nt][2] *= ch; o[nt][3] *= ch;
        }

        // ---- exp + sums + stage P into permuted cols ----
#pragma unroll
        for (int nt = 0; nt < 8; nt++) {
            float p0 = __expf(s[nt][0] - mnl);
            float p1 = __expf(s[nt][1] - mnl);
            float p2 = __expf(s[nt][2] - mnh);
            float p3 = __expf(s[nt][3] - mnh);
            llo += p0 + p1; lhi += p2 + p3;
            int cb = nt*8;
            sPw[(g  )*SPS + cb + pc0] = f2tf(p0);
            sPw[(g  )*SPS + cb + pc1] = f2tf(p1);
            sPw[(g+8)*SPS + cb + pc0] = f2tf(p2);
            sPw[(g+8)*SPS + cb + pc1] = f2tf(p3);
        }
        __syncwarp();

        // ---- O += P V ----
        unsigned pa[8][4];
#pragma unroll
        for (int kt = 0; kt < 8; kt++) {
            uint2 lo = *(const uint2*)&sPw[(g  )*SPS + kt*8 + 2*tig];
            uint2 hi = *(const uint2*)&sPw[(g+8)*SPS + kt*8 + 2*tig];
            pa[kt][0] = lo.x; pa[kt][2] = lo.y;
            pa[kt][1] = hi.x; pa[kt][3] = hi.y;
        }
#pragma unroll
        for (int nt = 0; nt < 8; nt++) {
#pragma unroll
            for (int kt = 0; kt < 8; kt++) {
                uint2 bb = *(const uint2*)&uV[(nt*8+g)*SVT + kt*8 + 2*tig];
                mma_tf32(o[nt], pa[kt], bb.x, bb.y);
            }
        }
        __syncthreads();
    }

    // ---- finalize ----
    llo += __shfl_xor_sync(0xffffffff, llo, 1);
    llo += __shfl_xor_sync(0xffffffff, llo, 2);
    lhi += __shfl_xor_sync(0xffffffff, lhi, 1);
    lhi += __shfl_xor_sync(0xffffffff, lhi, 2);
    float invl = 1.f / llo, invh = 1.f / lhi;

    int row_lo = q0 + qb + g;
    int row_hi = row_lo + 8;
    float* out_lo = out + ((size_t)(b * SEQ + row_lo)) * HIDDEN + h * HD;
    float* out_hi = out + ((size_t)(b * SEQ + row_hi)) * HIDDEN + h * HD;
#pragma unroll
    for (int nt = 0; nt < 8; nt++) {
        int d = nt*8 + 2*tig;
        *(float2*)(out_lo + d) = make_float2(o[nt][0] * invl, o[nt][1] * invl);
        *(float2*)(out_hi + d) = make_float2(o[nt][2] * invh, o[nt][3] * invh);
    }
}

// ---------------------------------------------------------------------------
extern "C" void kernel_launch(void* const* d_in, const int* in_sizes, int n_in,
                              void* d_out, int out_size) {
    const float* X    = (const float*)d_in[0];
    const float* mask = (const float*)d_in[1];
    const float* Wq = (const float*)d_in[2];  const float* bq = (const float*)d_in[3];
    const float* Aq = (const float*)d_in[4];  const float* Bq = (const float*)d_in[5];
    const float* Wk = (const float*)d_in[6];  const float* bk = (const float*)d_in[7];
    const float* Ak = (const float*)d_in[8];  const float* Bk = (const float*)d_in[9];
    const float* Wv = (const float*)d_in[10]; const float* bv = (const float*)d_in[11];
    const float* Av = (const float*)d_in[12]; const float* Bv = (const float*)d_in[13];
    float* out = (float*)d_out;

    weff_kernel<<<(NPROJ*HIDDEN*HIDDEN)/256, 256>>>(Wq, Aq, Bq, Wk, Ak, Bk, Wv, Av, Bv);
    xtf_kernel<<<(BSZ*SEQ*HIDDEN/4)/256, 256>>>(X);

    static bool attr_done = false;
    if (!attr_done) {
        cudaFuncSetAttribute(qkv_gemm_tf32, cudaFuncAttributeMaxDynamicSharedMemorySize, 2*2*SAB*4);
        cudaFuncSetAttribute(attn_tf32,     cudaFuncAttributeMaxDynamicSharedMemorySize, ATTN_SMEM);
        attr_done = true;
    }

    dim3 g2(NPROJ*HIDDEN/128, (BSZ*SEQ)/128);   // (24, 64)
    qkv_gemm_tf32<<<g2, 256, 2*2*SAB*4>>>(bq, bk, bv);

    dim3 g3(SEQ/64, BH);                         // (32, 64)
    attn_tf32<<<g3, 128, ATTN_SMEM>>>(mask, out);
}

// round 5
// speedup vs baseline: 1.2134x; 1.2134x over previous
#include <cuda_runtime.h>

#define HIDDEN 1024
#define HEADS 16
#define HD 64
#define RANK 16
#define BSZ 4
#define SEQ 2048
#define BH (BSZ*HEADS)          // 64
#define NPROJ 3
#define LORA_SCALE (1.0f/16.0f)
#define SM_SCALE 0.125f          // 1/sqrt(64)

// k-permutation within 8-groups: pos(c) = ((c&3)<<1)|((c>>2)&1)  -> pairs (t,t+4) adjacent
#define PERM8(c) ( ((c) & ~7) | ((((c)&3)<<1) | (((c)>>2)&1)) )

// Scratch
__device__ float g_Weff[(size_t)NPROJ*HIDDEN*HIDDEN];   // tf32 bits, k-permuted
__device__ float g_Xtf [(size_t)BSZ*SEQ*HIDDEN];        // tf32 bits, k-permuted
__device__ float g_QKV [(size_t)NPROJ*BH*SEQ*HD];       // Q,K: [bh][s][d'] d-permuted; V: [bh][d][s] transposed, natural

// ---------------------------------------------------------------------------
__device__ __forceinline__ unsigned f2tf(float f) {
    unsigned u;
    asm("cvt.rna.tf32.f32 %0, %1;" : "=r"(u) : "f"(f));
    return u;
}
__device__ __forceinline__ float f2tf_f(float f) { return __uint_as_float(f2tf(f)); }

__device__ __forceinline__ void mma_tf32(float c[4], const unsigned a[4], unsigned b0, unsigned b1) {
    asm volatile(
        "mma.sync.aligned.m16n8k8.row.col.f32.tf32.tf32.f32 "
        "{%0,%1,%2,%3},{%4,%5,%6,%7},{%8,%9},{%0,%1,%2,%3};"
        : "+f"(c[0]), "+f"(c[1]), "+f"(c[2]), "+f"(c[3])
        : "r"(a[0]), "r"(a[1]), "r"(a[2]), "r"(a[3]), "r"(b0), "r"(b1));
}
__device__ __forceinline__ void cpa16(float* dst, const float* src) {
    unsigned a = (unsigned)__cvta_generic_to_shared(dst);
    asm volatile("cp.async.cg.shared.global [%0], [%1], 16;" :: "r"(a), "l"(src));
}
#define CP_COMMIT asm volatile("cp.async.commit_group;")
#define CP_WAIT0  asm volatile("cp.async.wait_group 0;")
#define CP_WAIT1  asm volatile("cp.async.wait_group 1;")

// ---------------------------------------------------------------------------
// Kernel 1a: W_eff = tf32(W + (1/16) B A), stored k-permuted
// ---------------------------------------------------------------------------
__global__ void weff_kernel(const float* __restrict__ Wq, const float* __restrict__ Aq, const float* __restrict__ Bq,
                            const float* __restrict__ Wk, const float* __restrict__ Ak, const float* __restrict__ Bk,
                            const float* __restrict__ Wv, const float* __restrict__ Av, const float* __restrict__ Bv) {
    int idx = blockIdx.x * blockDim.x + threadIdx.x;
    if (idx >= NPROJ*HIDDEN*HIDDEN) return;
    int p  = idx >> 20;
    int nk = idx & ((1 << 20) - 1);
    int n  = nk >> 10;
    int k  = nk & 1023;
    const float* W = (p == 0) ? Wq : ((p == 1) ? Wk : Wv);
    const float* A = (p == 0) ? Aq : ((p == 1) ? Ak : Av);
    const float* B = (p == 0) ? Bq : ((p == 1) ? Bk : Bv);
    float acc = 0.f;
#pragma unroll
    for (int r = 0; r < RANK; r++) acc += B[n*RANK + r] * A[r*HIDDEN + k];
    g_Weff[((size_t)p << 20) + ((size_t)n << 10) + PERM8(k)] = f2tf_f(W[nk] + LORA_SCALE * acc);
}

// ---------------------------------------------------------------------------
// Kernel 1b: X -> tf32, k-permuted
// ---------------------------------------------------------------------------
__global__ void xtf_kernel(const float* __restrict__ X) {
    int i  = blockIdx.x * blockDim.x + threadIdx.x;   // float4 index
    int c4 = (i << 2) & 1023;
    size_t row = ((size_t)(i << 2)) & ~1023ull;
    float4 v = ((const float4*)X)[i];
    float* dst = g_Xtf + row;
    dst[PERM8(c4+0)] = f2tf_f(v.x);
    dst[PERM8(c4+1)] = f2tf_f(v.y);
    dst[PERM8(c4+2)] = f2tf_f(v.z);
    dst[PERM8(c4+3)] = f2tf_f(v.w);
}

// ---------------------------------------------------------------------------
// Kernel 2: QKV GEMM, mma tf32, cp.async 2-stage, LDS.64 fragments.
// ---------------------------------------------------------------------------
#define GST 40
#define SAB (128*GST)

__global__ __launch_bounds__(256) void qkv_gemm_tf32(const float* __restrict__ bq,
                                                     const float* __restrict__ bk,
                                                     const float* __restrict__ bv) {
    extern __shared__ __align__(16) float gsm[];
    int tid  = threadIdx.x;
    int lane = tid & 31;
    int wid  = tid >> 5;
    int wm   = wid & 3;
    int wn   = wid >> 2;
    int g    = lane >> 2;
    int tig  = lane & 3;
    int m0 = blockIdx.y * 128;
    int n0 = blockIdx.x * 128;

    float acc[2][8][4];
#pragma unroll
    for (int mt = 0; mt < 2; mt++)
#pragma unroll
        for (int nt = 0; nt < 8; nt++)
#pragma unroll
            for (int i = 0; i < 4; i++) acc[mt][nt][i] = 0.f;

    int frow = tid >> 3;
    int fc4  = (tid & 7) << 2;

#define ISSUE(slab, buf) do {                                                     \
        float* sA_ = gsm + (buf)*2*SAB;                                           \
        float* sB_ = sA_ + SAB;                                                   \
        int kc_ = (slab)*32;                                                      \
        _Pragma("unroll")                                                         \
        for (int it = 0; it < 4; it++) {                                          \
            int row = frow + it*32;                                               \
            cpa16(sA_ + row*GST + fc4, g_Xtf  + (size_t)(m0+row)*HIDDEN + kc_ + fc4); \
            cpa16(sB_ + row*GST + fc4, g_Weff + (size_t)(n0+row)*HIDDEN + kc_ + fc4); \
        }                                                                         \
        CP_COMMIT;                                                                \
    } while (0)

    ISSUE(0, 0);

    for (int s = 0; s < HIDDEN/32; s++) {
        if (s + 1 < HIDDEN/32) { ISSUE(s+1, (s+1)&1); CP_WAIT1; }
        else                   { CP_WAIT0; }
        __syncthreads();

        const unsigned* uA = (const unsigned*)(gsm + (s&1)*2*SAB);
        const unsigned* uB = uA + SAB;
#pragma unroll
        for (int ks = 0; ks < 4; ks++) {
            int k0 = ks * 8;
            unsigned a[2][4], b[8][2];
#pragma unroll
            for (int mt = 0; mt < 2; mt++) {
                int rb = wm*32 + mt*16;
                uint2 lo = *(const uint2*)&uA[(rb+g  )*GST + k0 + 2*tig];
                uint2 hi = *(const uint2*)&uA[(rb+g+8)*GST + k0 + 2*tig];
                a[mt][0] = lo.x; a[mt][2] = lo.y;
                a[mt][1] = hi.x; a[mt][3] = hi.y;
            }
#pragma unroll
            for (int nt = 0; nt < 8; nt++) {
                int cb = wn*64 + nt*8;
                uint2 bb = *(const uint2*)&uB[(cb+g)*GST + k0 + 2*tig];
                b[nt][0] = bb.x; b[nt][1] = bb.y;
            }
#pragma unroll
            for (int mt = 0; mt < 2; mt++)
#pragma unroll
                for (int nt = 0; nt < 8; nt++)
                    mma_tf32(acc[mt][nt], a[mt], b[nt][0], b[nt][1]);
        }
        __syncthreads();
    }

    // epilogue: bias + tf32 round; Q,K -> [bh][s][perm d]; V -> [bh][d][s] (transposed, natural)
#pragma unroll
    for (int mt = 0; mt < 2; mt++) {
#pragma unroll
        for (int half = 0; half < 2; half++) {
            int m  = m0 + wm*32 + mt*16 + g + half*8;
            int b  = m >> 11;
            int sq = m & 2047;
#pragma unroll
            for (int nt = 0; nt < 8; nt++) {
                int n  = n0 + wn*64 + nt*8 + 2*tig;
                int p  = n >> 10;
                int hn = n & 1023;
                int h  = hn >> 6;
                int d  = n & 63;
                const float* bias = (p == 0) ? bq : ((p == 1) ? bk : bv);
                float v0 = f2tf_f(acc[mt][nt][half*2 + 0] + bias[hn]);
                float v1 = f2tf_f(acc[mt][nt][half*2 + 1] + bias[hn + 1]);
                int bh = b*HEADS + h;
                if (p < 2) {
                    float* dst = &g_QKV[(((size_t)p * BH + bh) * SEQ + sq) * HD];
                    dst[PERM8(d)]   = v0;
                    dst[PERM8(d+1)] = v1;
                } else {
                    float* dst = &g_QKV[(size_t)2*BH*SEQ*HD + ((size_t)bh * HD) * SEQ + sq];
                    dst[(size_t)d    *SEQ] = v0;
                    dst[(size_t)(d+1)*SEQ] = v1;
                }
            }
        }
    }
}

// ---------------------------------------------------------------------------
// Kernel 3: flash attention, mma tf32.  P never touches smem (C->A frag
// identity via contraction permutation sigma: slot t->col 2t, t+4->col 2t+1).
// K/V double-buffered cp.async, pipelined one tile ahead.
// ---------------------------------------------------------------------------
#define SKS 72
#define SVT 72
#define KV_WORDS (64*SKS + 64*SVT)
#define ATTN_SMEM ((2*KV_WORDS + 2*64) * 4)

__global__ __launch_bounds__(128, 3) void attn_tf32(const float* __restrict__ mask,
                                                    float* __restrict__ out) {
    extern __shared__ __align__(16) float asm_[];
    // buf b: sK = asm_ + b*KV_WORDS, sVt = sK + 64*SKS
    float* sMb = asm_ + 2*KV_WORDS;     // [2][64]

    int bh = blockIdx.y;
    int b  = bh >> 4;
    int h  = bh & 15;
    int q0 = blockIdx.x * 64;
    int tid  = threadIdx.x;
    int w    = tid >> 5;
    int lane = tid & 31;
    int g    = lane >> 2;
    int tig  = lane & 3;

    const float* maskb = mask + b * SEQ;
    const float* Kg0 = g_QKV + ((size_t)(BH + bh) * SEQ) * HD;
    const float* Vg0 = g_QKV + (size_t)2*BH*SEQ*HD + (size_t)bh * HD * SEQ;

    // ---- stage Q (64x64, d-permuted) into buf0's sK region ----
    {
        const float* Qg = g_QKV + ((size_t)bh * SEQ + q0) * HD;
#pragma unroll
        for (int it = 0; it < 4; it++) {
            int f   = tid + it * 128;          // 512 float4s
            int row = f >> 2;
            int c4  = (f & 3) << 4;
            cpa16(asm_ + row*SKS + c4,      Qg + row*HD + c4);
            cpa16(asm_ + row*SKS + c4 + 4,  Qg + row*HD + c4 + 4);  // hmm; keep simple below
        }
    }
    // (simpler restage: 8 chunks of 16B per row via 128 threads x 8 iters)
    __syncthreads();   // harmless; real staging below

    // redo cleanly: 64 rows x 16 float4
    {
        const float* Qg = g_QKV + ((size_t)bh * SEQ + q0) * HD;
#pragma unroll
        for (int it = 0; it < 8; it++) {
            int f   = tid + it * 128;
            int row = f >> 4;
            int c4  = (f & 15) << 2;
            cpa16(asm_ + row*SKS + c4, Qg + row*HD + c4);
        }
        CP_COMMIT; CP_WAIT0;
    }
    __syncthreads();

    unsigned qa[8][4];
    int qb = w * 16;
    {
        const unsigned* uQ = (const unsigned*)asm_;
#pragma unroll
        for (int kt = 0; kt < 8; kt++) {
            uint2 lo = *(const uint2*)&uQ[(qb+g  )*SKS + kt*8 + 2*tig];
            uint2 hi = *(const uint2*)&uQ[(qb+g+8)*SKS + kt*8 + 2*tig];
            qa[kt][0] = lo.x; qa[kt][2] = lo.y;
            qa[kt][1] = hi.x; qa[kt][3] = hi.y;
        }
    }
    __syncthreads();   // all warps have Q; buf0 reusable

    float o[8][4];
#pragma unroll
    for (int nt = 0; nt < 8; nt++)
#pragma unroll
        for (int i = 0; i < 4; i++) o[nt][i] = 0.f;
    float mlo = -1e30f, mhi = -1e30f, llo = 0.f, lhi = 0.f;

    // issue one K/V tile + mask into buffer
#define AISSUE(ti, bf) do {                                                        \
        float* sK_ = asm_ + (bf)*KV_WORDS;                                         \
        float* sV_ = sK_ + 64*SKS;                                                 \
        int kt_ = (ti)*64;                                                         \
        _Pragma("unroll")                                                          \
        for (int it = 0; it < 8; it++) {                                           \
            int f   = tid + it * 128;                                              \
            int row = f >> 4;                                                      \
            int c4  = (f & 15) << 2;                                               \
            cpa16(sK_ + row*SKS + c4, Kg0 + (size_t)(kt_ + row)*HD + c4);          \
            cpa16(sV_ + row*SVT + c4, Vg0 + (size_t)row*SEQ + kt_ + c4);           \
        }                                                                          \
        if (tid < 16) cpa16(sMb + (bf)*64 + tid*4, maskb + kt_ + tid*4);           \
        CP_COMMIT;                                                                 \
    } while (0)

    AISSUE(0, 0);

    for (int ti = 0; ti < SEQ/64; ti++) {
        int bf = ti & 1;
        if (ti + 1 < SEQ/64) { AISSUE(ti+1, bf^1); CP_WAIT1; }
        else                 { CP_WAIT0; }
        __syncthreads();

        const unsigned* uK = (const unsigned*)(asm_ + bf*KV_WORDS);
        const unsigned* uV = uK + 64*SKS;
        const float*    sM = sMb + bf*64;

        // ---- S = Q K^T ----
        float s[8][4];
#pragma unroll
        for (int nt = 0; nt < 8; nt++) {
            s[nt][0] = s[nt][1] = s[nt][2] = s[nt][3] = 0.f;
#pragma unroll
            for (int kt = 0; kt < 8; kt++) {
                uint2 bb = *(const uint2*)&uK[(nt*8+g)*SKS + kt*8 + 2*tig];
                mma_tf32(s[nt], qa[kt], bb.x, bb.y);
            }
        }

        // ---- scale + mask + tile max ----
        float tml = -1e30f, tmh = -1e30f;
#pragma unroll
        for (int nt = 0; nt < 8; nt++) {
            int c = nt*8 + 2*tig;
            float m0v = sM[c], m1v = sM[c+1];
            s[nt][0] = s[nt][0] * SM_SCALE + m0v;
            s[nt][1] = s[nt][1] * SM_SCALE + m1v;
            s[nt][2] = s[nt][2] * SM_SCALE + m0v;
            s[nt][3] = s[nt][3] * SM_SCALE + m1v;
            tml = fmaxf(tml, fmaxf(s[nt][0], s[nt][1]));
            tmh = fmaxf(tmh, fmaxf(s[nt][2], s[nt][3]));
        }
        tml = fmaxf(tml, __shfl_xor_sync(0xffffffff, tml, 1));
        tml = fmaxf(tml, __shfl_xor_sync(0xffffffff, tml, 2));
        tmh = fmaxf(tmh, __shfl_xor_sync(0xffffffff, tmh, 1));
        tmh = fmaxf(tmh, __shfl_xor_sync(0xffffffff, tmh, 2));

        float mnl = fmaxf(mlo, tml), mnh = fmaxf(mhi, tmh);
        float cl = __expf(mlo - mnl), ch = __expf(mhi - mnh);
        llo *= cl; lhi *= ch;
        mlo = mnl; mhi = mnh;
#pragma unroll
        for (int nt = 0; nt < 8; nt++) {
            o[nt][0] *= cl; o[nt][1] *= cl;
            o[nt][2] *= ch; o[nt][3] *= ch;
        }

        // ---- exp -> P A-fragments directly in registers (sigma permutation) ----
        unsigned pa[8][4];
#pragma unroll
        for (int kt = 0; kt < 8; kt++) {
            float p0 = __expf(s[kt][0] - mnl);   // row g,   col 2tig   -> slot tig
            float p1 = __expf(s[kt][1] - mnl);   // row g,   col 2tig+1 -> slot tig+4
            float p2 = __expf(s[kt][2] - mnh);   // row g+8, col 2tig   -> slot tig
            float p3 = __expf(s[kt][3] - mnh);   // row g+8, col 2tig+1 -> slot tig+4
            llo += p0 + p1; lhi += p2 + p3;
            pa[kt][0] = f2tf(p0);
            pa[kt][1] = f2tf(p2);
            pa[kt][2] = f2tf(p1);
            pa[kt][3] = f2tf(p3);
        }

        // ---- O += P V  (V rows in sigma order = natural pairs 2tig,2tig+1) ----
#pragma unroll
        for (int nt = 0; nt < 8; nt++) {
#pragma unroll
            for (int kt = 0; kt < 8; kt++) {
                uint2 bb = *(const uint2*)&uV[(nt*8+g)*SVT + kt*8 + 2*tig];
                mma_tf32(o[nt], pa[kt], bb.x, bb.y);
            }
        }
        __syncthreads();
    }

    // ---- finalize ----
    llo += __shfl_xor_sync(0xffffffff, llo, 1);
    llo += __shfl_xor_sync(0xffffffff, llo, 2);
    lhi += __shfl_xor_sync(0xffffffff, lhi, 1);
    lhi += __shfl_xor_sync(0xffffffff, lhi, 2);
    float invl = 1.f / llo, invh = 1.f / lhi;

    int row_lo = q0 + qb + g;
    int row_hi = row_lo + 8;
    float* out_lo = out + ((size_t)(b * SEQ + row_lo)) * HIDDEN + h * HD;
    float* out_hi = out + ((size_t)(b * SEQ + row_hi)) * HIDDEN + h * HD;
#pragma unroll
    for (int nt = 0; nt < 8; nt++) {
        int d = nt*8 + 2*tig;
        *(float2*)(out_lo + d) = make_float2(o[nt][0] * invl, o[nt][1] * invl);
        *(float2*)(out_hi + d) = make_float2(o[nt][2] * invh, o[nt][3] * invh);
    }
}

// ---------------------------------------------------------------------------
extern "C" void kernel_launch(void* const* d_in, const int* in_sizes, int n_in,
                              void* d_out, int out_size) {
    const float* X    = (const float*)d_in[0];
    const float* mask = (const float*)d_in[1];
    const float* Wq = (const float*)d_in[2];  const float* bq = (const float*)d_in[3];
    const float* Aq = (const float*)d_in[4];  const float* Bq = (const float*)d_in[5];
    const float* Wk = (const float*)d_in[6];  const float* bk = (const float*)d_in[7];
    const float* Ak = (const float*)d_in[8];  const float* bk2 = bk; (void)bk2;
    const float* Bk = (const float*)d_in[9];
    const float* Wv = (const float*)d_in[10]; const float* bv = (const float*)d_in[11];
    const float* Av = (const float*)d_in[12]; const float* Bv = (const float*)d_in[13];
    float* out = (float*)d_out;

    weff_kernel<<<(NPROJ*HIDDEN*HIDDEN)/256, 256>>>(Wq, Aq, Bq, Wk, Ak, Bk, Wv, Av, Bv);
    xtf_kernel<<<(BSZ*SEQ*HIDDEN/4)/256, 256>>>(X);

    static bool attr_done = false;
    if (!attr_done) {
        cudaFuncSetAttribute(qkv_gemm_tf32, cudaFuncAttributeMaxDynamicSharedMemorySize, 2*2*SAB*4);
        cudaFuncSetAttribute(attn_tf32,     cudaFuncAttributeMaxDynamicSharedMemorySize, ATTN_SMEM);
        attr_done = true;
    }

    dim3 g2(NPROJ*HIDDEN/128, (BSZ*SEQ)/128);   // (24, 64)
    qkv_gemm_tf32<<<g2, 256, 2*2*SAB*4>>>(bq, bk, bv);

    dim3 g3(SEQ/64, BH);                         // (32, 64)
    attn_tf32<<<g3, 128, ATTN_SMEM>>>(mask, out);
}

// round 6
// speedup vs baseline: 2.1035x; 1.7335x over previous
#include <cuda_runtime.h>
#include <cuda_fp16.h>

#define HIDDEN 1024
#define HEADS 16
#define HD 64
#define RANK 16
#define BSZ 4
#define SEQ 2048
#define BH (BSZ*HEADS)          // 64
#define NPROJ 3
#define LORA_SCALE (1.0f/16.0f)
#define SM_SCALE 0.125f          // 1/sqrt(64)

// PERM16: within 16-group, place k-slots (2t,2t+1,2t+8,2t+9) adjacent at 4t..4t+3
__device__ __host__ __forceinline__ int perm16(int r) {
    return (r < 8) ? (((r >> 1) << 2) | (r & 1))
                   : ((((r - 8) >> 1) << 2) + 2 + (r & 1));
}
#define PERM16F(k) (((k) & ~15) | perm16((k) & 15))

// Scratch (no allocations allowed)
__device__ __half g_Wh  [(size_t)NPROJ*HIDDEN*HIDDEN];  // fp16, k-perm16
__device__ __half g_Xh  [(size_t)BSZ*SEQ*HIDDEN];       // fp16, k-perm16
__device__ __half g_QKVh[(size_t)NPROJ*BH*SEQ*HD];      // Q,K: [bh][s][perm16 d]; V: [bh][d][perm16-block s]

// ---------------------------------------------------------------------------
__device__ __forceinline__ void mma_f16(float c[4], const unsigned a[4], unsigned b0, unsigned b1) {
    asm volatile(
        "mma.sync.aligned.m16n8k16.row.col.f32.f16.f16.f32 "
        "{%0,%1,%2,%3},{%4,%5,%6,%7},{%8,%9},{%0,%1,%2,%3};"
        : "+f"(c[0]), "+f"(c[1]), "+f"(c[2]), "+f"(c[3])
        : "r"(a[0]), "r"(a[1]), "r"(a[2]), "r"(a[3]), "r"(b0), "r"(b1));
}
__device__ __forceinline__ unsigned pack2(float lo, float hi) {
    __half2 h = __floats2half2_rn(lo, hi);
    return *(unsigned*)&h;
}
__device__ __forceinline__ void cpa16(void* dst, const void* src) {
    unsigned a = (unsigned)__cvta_generic_to_shared(dst);
    asm volatile("cp.async.cg.shared.global [%0], [%1], 16;" :: "r"(a), "l"(src));
}
#define CP_COMMIT asm volatile("cp.async.commit_group;")
#define CP_WAIT0  asm volatile("cp.async.wait_group 0;")
#define CP_WAIT1  asm volatile("cp.async.wait_group 1;")

// ---------------------------------------------------------------------------
// Kernel 1a: W_eff = fp16(W + (1/16) B A), k-perm16
// ---------------------------------------------------------------------------
__global__ void weff_kernel(const float* __restrict__ Wq, const float* __restrict__ Aq, const float* __restrict__ Bq,
                            const float* __restrict__ Wk, const float* __restrict__ Ak, const float* __restrict__ Bk,
                            const float* __restrict__ Wv, const float* __restrict__ Av, const float* __restrict__ Bv) {
    int idx = blockIdx.x * blockDim.x + threadIdx.x;
    if (idx >= NPROJ*HIDDEN*HIDDEN) return;
    int p  = idx >> 20;
    int nk = idx & ((1 << 20) - 1);
    int n  = nk >> 10;
    int k  = nk & 1023;
    const float* W = (p == 0) ? Wq : ((p == 1) ? Wk : Wv);
    const float* A = (p == 0) ? Aq : ((p == 1) ? Ak : Av);
    const float* B = (p == 0) ? Bq : ((p == 1) ? Bk : Bv);
    float acc = 0.f;
#pragma unroll
    for (int r = 0; r < RANK; r++) acc += B[n*RANK + r] * A[r*HIDDEN + k];
    g_Wh[((size_t)p << 20) + ((size_t)n << 10) + PERM16F(k)] = __float2half_rn(W[nk] + LORA_SCALE * acc);
}

// ---------------------------------------------------------------------------
// Kernel 1b: X -> fp16, k-perm16
// ---------------------------------------------------------------------------
__global__ void xh_kernel(const float* __restrict__ X) {
    int i = blockIdx.x * blockDim.x + threadIdx.x;   // float4 index
    int base = i << 2;
    float4 v = ((const float4*)X)[i];
    __half* dst = g_Xh + (size_t)(base & ~15);
    int r = base & 15;       // 0,4,8,12
    dst[perm16(r+0)] = __float2half_rn(v.x);
    dst[perm16(r+1)] = __float2half_rn(v.y);
    dst[perm16(r+2)] = __float2half_rn(v.z);
    dst[perm16(r+3)] = __float2half_rn(v.w);
}

// ---------------------------------------------------------------------------
// Kernel 2: QKV GEMM, mma fp16 m16n8k16, cp.async 2-stage, K-slab 64.
// ---------------------------------------------------------------------------
#define GST 80                 // smem stride (halves); row step = 40 words = 8 banks mod 32
#define SABH (128*GST)         // halves per matrix per buffer

__global__ __launch_bounds__(256) void qkv_gemm_f16(const float* __restrict__ bq,
                                                    const float* __restrict__ bk,
                                                    const float* __restrict__ bv) {
    extern __shared__ __align__(16) __half gsm[];
    int tid  = threadIdx.x;
    int lane = tid & 31;
    int wid  = tid >> 5;
    int wm   = wid & 3;
    int wn   = wid >> 2;
    int g    = lane >> 2;
    int tig  = lane & 3;
    int m0 = blockIdx.y * 128;
    int n0 = blockIdx.x * 128;

    float acc[2][8][4];
#pragma unroll
    for (int mt = 0; mt < 2; mt++)
#pragma unroll
        for (int nt = 0; nt < 8; nt++)
#pragma unroll
            for (int i = 0; i < 4; i++) acc[mt][nt][i] = 0.f;

#define ISSUE(slab, buf) do {                                                      \
        __half* sA_ = gsm + (buf)*2*SABH;                                          \
        __half* sB_ = sA_ + SABH;                                                  \
        int kc_ = (slab)*64;                                                       \
        _Pragma("unroll")                                                          \
        for (int it = 0; it < 4; it++) {                                           \
            int f   = tid + it * 256;          /* 1024 chunks of 8 halves */       \
            int row = f >> 3;                                                      \
            int ch  = (f & 7) << 3;                                                \
            cpa16(sA_ + row*GST + ch, g_Xh + (size_t)(m0+row)*HIDDEN + kc_ + ch);  \
            cpa16(sB_ + row*GST + ch, g_Wh + (size_t)(n0+row)*HIDDEN + kc_ + ch);  \
        }                                                                          \
        CP_COMMIT;                                                                 \
    } while (0)

    ISSUE(0, 0);

    for (int s = 0; s < HIDDEN/64; s++) {
        if (s + 1 < HIDDEN/64) { ISSUE(s+1, (s+1)&1); CP_WAIT1; }
        else                   { CP_WAIT0; }
        __syncthreads();

        const __half* hA = gsm + (s&1)*2*SABH;
        const __half* hB = hA + SABH;
#pragma unroll
        for (int ks = 0; ks < 4; ks++) {
            int ko = ks*16 + 4*tig;
            unsigned a[2][4], b[8][2];
#pragma unroll
            for (int mt = 0; mt < 2; mt++) {
                int rb = wm*32 + mt*16;
                uint2 lo = *(const uint2*)&hA[(rb+g  )*GST + ko];
                uint2 hi = *(const uint2*)&hA[(rb+g+8)*GST + ko];
                a[mt][0] = lo.x; a[mt][1] = hi.x;
                a[mt][2] = lo.y; a[mt][3] = hi.y;
            }
#pragma unroll
            for (int nt = 0; nt < 8; nt++) {
                int cb = wn*64 + nt*8;
                uint2 bb = *(const uint2*)&hB[(cb+g)*GST + ko];
                b[nt][0] = bb.x; b[nt][1] = bb.y;
            }
#pragma unroll
            for (int mt = 0; mt < 2; mt++)
#pragma unroll
                for (int nt = 0; nt < 8; nt++)
                    mma_f16(acc[mt][nt], a[mt], b[nt][0], b[nt][1]);
        }
        __syncthreads();
    }

    // epilogue: bias + fp16 round; Q,K -> [bh][s][perm16 d]; V -> [bh][d][perm16-block s]
#pragma unroll
    for (int mt = 0; mt < 2; mt++) {
#pragma unroll
        for (int half = 0; half < 2; half++) {
            int m  = m0 + wm*32 + mt*16 + g + half*8;
            int b  = m >> 11;
            int sq = m & 2047;
            int sp = (sq & ~15) | perm16(sq & 15);
#pragma unroll
            for (int nt = 0; nt < 8; nt++) {
                int n  = n0 + wn*64 + nt*8 + 2*tig;
                int p  = n >> 10;
                int hn = n & 1023;
                int h  = hn >> 6;
                int d  = n & 63;
                const float* bias = (p == 0) ? bq : ((p == 1) ? bk : bv);
                float v0 = acc[mt][nt][half*2 + 0] + bias[hn];
                float v1 = acc[mt][nt][half*2 + 1] + bias[hn + 1];
                int bh = b*HEADS + h;
                if (p < 2) {
                    __half* dst = &g_QKVh[(((size_t)p * BH + bh) * SEQ + sq) * HD + PERM16F(d)];
                    *(__half2*)dst = __floats2half2_rn(v0, v1);   // perm positions are adjacent for even d
                } else {
                    __half* dst = &g_QKVh[(size_t)2*BH*SEQ*HD + ((size_t)bh*HD + d) * SEQ + sp];
                    dst[0]   = __float2half_rn(v0);
                    dst[SEQ] = __float2half_rn(v1);
                }
            }
        }
    }
}

// ---------------------------------------------------------------------------
// Kernel 3: flash attention, mma fp16.  P stays in registers (C->A identity).
// K/V double-buffered cp.async, pipelined one tile ahead.
// ---------------------------------------------------------------------------
#define SKH 80                       // halves stride
#define KVBH (2*64*SKH)              // halves per buffer (K + V)
#define ATTN_SMEM (2*KVBH*2 + 2*64*4)   // bytes

__global__ __launch_bounds__(128, 3) void attn_f16(const float* __restrict__ mask,
                                                   float* __restrict__ out) {
    extern __shared__ __align__(16) char smem_[];
    __half* sKV = (__half*)smem_;                    // [2][K 64*SKH | V 64*SKH]
    float*  sMb = (float*)(smem_ + 2*KVBH*2);        // [2][64]

    int bh = blockIdx.y;
    int b  = bh >> 4;
    int h  = bh & 15;
    int q0 = blockIdx.x * 64;
    int tid  = threadIdx.x;
    int w    = tid >> 5;
    int lane = tid & 31;
    int g    = lane >> 2;
    int tig  = lane & 3;

    const float* maskb = mask + b * SEQ;
    const __half* Kg0 = g_QKVh + ((size_t)(BH + bh) * SEQ) * HD;
    const __half* Vg0 = g_QKVh + (size_t)2*BH*SEQ*HD + (size_t)bh * HD * SEQ;

    // ---- stage Q (64 rows x 64 halves, perm16 d) into buf0 K region ----
    {
        const __half* Qg = g_QKVh + ((size_t)bh * SEQ + q0) * HD;
#pragma unroll
        for (int it = 0; it < 4; it++) {
            int f   = tid + it * 128;       // 512 chunks
            int row = f >> 3;
            int ch  = (f & 7) << 3;
            cpa16(sKV + row*SKH + ch, Qg + row*HD + ch);
        }
        CP_COMMIT; CP_WAIT0;
    }
    __syncthreads();

    unsigned qa[4][4];
    int qb = w * 16;
#pragma unroll
    for (int ks = 0; ks < 4; ks++) {
        int ko = ks*16 + 4*tig;
        uint2 lo = *(const uint2*)&sKV[(qb+g  )*SKH + ko];
        uint2 hi = *(const uint2*)&sKV[(qb+g+8)*SKH + ko];
        qa[ks][0] = lo.x; qa[ks][1] = hi.x;
        qa[ks][2] = lo.y; qa[ks][3] = hi.y;
    }
    __syncthreads();   // buf0 reusable

    float o[8][4];
#pragma unroll
    for (int nt = 0; nt < 8; nt++)
#pragma unroll
        for (int i = 0; i < 4; i++) o[nt][i] = 0.f;
    float mlo = -1e30f, mhi = -1e30f, llo = 0.f, lhi = 0.f;

#define AISSUE(ti, bf) do {                                                        \
        __half* sK_ = sKV + (bf)*KVBH;                                             \
        __half* sV_ = sK_ + 64*SKH;                                                \
        int kt_ = (ti)*64;                                                         \
        _Pragma("unroll")                                                          \
        for (int it = 0; it < 4; it++) {                                           \
            int f   = tid + it * 128;                                              \
            int row = f >> 3;                                                      \
            int ch  = (f & 7) << 3;                                                \
            cpa16(sK_ + row*SKH + ch, Kg0 + (size_t)(kt_ + row)*HD + ch);          \
            cpa16(sV_ + row*SKH + ch, Vg0 + (size_t)row*SEQ + kt_ + ch);           \
        }                                                                          \
        if (tid < 16) cpa16(sMb + (bf)*64 + tid*4, maskb + kt_ + tid*4);           \
        CP_COMMIT;                                                                 \
    } while (0)

    AISSUE(0, 0);

    for (int ti = 0; ti < SEQ/64; ti++) {
        int bf = ti & 1;
        if (ti + 1 < SEQ/64) { AISSUE(ti+1, bf^1); CP_WAIT1; }
        else                 { CP_WAIT0; }
        __syncthreads();

        const __half* uK = sKV + bf*KVBH;
        const __half* uV = uK + 64*SKH;
        const float*  sM = sMb + bf*64;

        // ---- S = Q K^T ----
        float s[8][4];
#pragma unroll
        for (int nt = 0; nt < 8; nt++) {
            s[nt][0] = s[nt][1] = s[nt][2] = s[nt][3] = 0.f;
#pragma unroll
            for (int ks = 0; ks < 4; ks++) {
                uint2 bb = *(const uint2*)&uK[(nt*8+g)*SKH + ks*16 + 4*tig];
                mma_f16(s[nt], qa[ks], bb.x, bb.y);
            }
        }

        // ---- scale + mask + tile max ----
        float tml = -1e30f, tmh = -1e30f;
#pragma unroll
        for (int nt = 0; nt < 8; nt++) {
            int c = nt*8 + 2*tig;
            float m0v = sM[c], m1v = sM[c+1];
            s[nt][0] = s[nt][0] * SM_SCALE + m0v;
            s[nt][1] = s[nt][1] * SM_SCALE + m1v;
            s[nt][2] = s[nt][2] * SM_SCALE + m0v;
            s[nt][3] = s[nt][3] * SM_SCALE + m1v;
            tml = fmaxf(tml, fmaxf(s[nt][0], s[nt][1]));
            tmh = fmaxf(tmh, fmaxf(s[nt][2], s[nt][3]));
        }
        tml = fmaxf(tml, __shfl_xor_sync(0xffffffff, tml, 1));
        tml = fmaxf(tml, __shfl_xor_sync(0xffffffff, tml, 2));
        tmh = fmaxf(tmh, __shfl_xor_sync(0xffffffff, tmh, 1));
        tmh = fmaxf(tmh, __shfl_xor_sync(0xffffffff, tmh, 2));

        float mnl = fmaxf(mlo, tml), mnh = fmaxf(mhi, tmh);
        float cl = __expf(mlo - mnl), ch = __expf(mhi - mnh);
        llo *= cl; lhi *= ch;
        mlo = mnl; mhi = mnh;
#pragma unroll
        for (int nt = 0; nt < 8; nt++) {
            o[nt][0] *= cl; o[nt][1] *= cl;
            o[nt][2] *= ch; o[nt][3] *= ch;
        }

        // ---- exp -> P A-fragments (natural layout for m16n8k16) ----
        float p[8][4];
#pragma unroll
        for (int nt = 0; nt < 8; nt++) {
            p[nt][0] = __expf(s[nt][0] - mnl);
            p[nt][1] = __expf(s[nt][1] - mnl);
            p[nt][2] = __expf(s[nt][2] - mnh);
            p[nt][3] = __expf(s[nt][3] - mnh);
            llo += p[nt][0] + p[nt][1];
            lhi += p[nt][2] + p[nt][3];
        }
        unsigned pa[4][4];
#pragma unroll
        for (int j = 0; j < 4; j++) {
            pa[j][0] = pack2(p[2*j  ][0], p[2*j  ][1]);
            pa[j][1] = pack2(p[2*j  ][2], p[2*j  ][3]);
            pa[j][2] = pack2(p[2*j+1][0], p[2*j+1][1]);
            pa[j][3] = pack2(p[2*j+1][2], p[2*j+1][3]);
        }

        // ---- O += P V  (V^T perm16 over keys) ----
#pragma unroll
        for (int nt = 0; nt < 8; nt++) {
#pragma unroll
            for (int j = 0; j < 4; j++) {
                uint2 bb = *(const uint2*)&uV[(nt*8+g)*SKH + j*16 + 4*tig];
                mma_f16(o[nt], pa[j], bb.x, bb.y);
            }
        }
        __syncthreads();
    }

    // ---- finalize ----
    llo += __shfl_xor_sync(0xffffffff, llo, 1);
    llo += __shfl_xor_sync(0xffffffff, llo, 2);
    lhi += __shfl_xor_sync(0xffffffff, lhi, 1);
    lhi += __shfl_xor_sync(0xffffffff, lhi, 2);
    float invl = 1.f / llo, invh = 1.f / lhi;

    int row_lo = q0 + qb + g;
    int row_hi = row_lo + 8;
    float* out_lo = out + ((size_t)(b * SEQ + row_lo)) * HIDDEN + h * HD;
    float* out_hi = out + ((size_t)(b * SEQ + row_hi)) * HIDDEN + h * HD;
#pragma unroll
    for (int nt = 0; nt < 8; nt++) {
        int d = nt*8 + 2*tig;
        *(float2*)(out_lo + d) = make_float2(o[nt][0] * invl, o[nt][1] * invl);
        *(float2*)(out_hi + d) = make_float2(o[nt][2] * invh, o[nt][3] * invh);
    }
}

// ---------------------------------------------------------------------------
extern "C" void kernel_launch(void* const* d_in, const int* in_sizes, int n_in,
                              void* d_out, int out_size) {
    const float* X    = (const float*)d_in[0];
    const float* mask = (const float*)d_in[1];
    const float* Wq = (const float*)d_in[2];  const float* bq = (const float*)d_in[3];
    const float* Aq = (const float*)d_in[4];  const float* Bq = (const float*)d_in[5];
    const float* Wk = (const float*)d_in[6];  const float* bk = (const float*)d_in[7];
    const float* Ak = (const float*)d_in[8];  const float* Bk = (const float*)d_in[9];
    const float* Wv = (const float*)d_in[10]; const float* bv = (const float*)d_in[11];
    const float* Av = (const float*)d_in[12]; const float* Bv = (const float*)d_in[13];
    float* out = (float*)d_out;

    weff_kernel<<<(NPROJ*HIDDEN*HIDDEN)/256, 256>>>(Wq, Aq, Bq, Wk, Ak, Bk, Wv, Av, Bv);
    xh_kernel<<<(BSZ*SEQ*HIDDEN/4)/256, 256>>>(X);

    static bool attr_done = false;
    if (!attr_done) {
        cudaFuncSetAttribute(qkv_gemm_f16, cudaFuncAttributeMaxDynamicSharedMemorySize, 2*2*SABH*2);
        cudaFuncSetAttribute(attn_f16,     cudaFuncAttributeMaxDynamicSharedMemorySize, ATTN_SMEM);
        attr_done = true;
    }

    dim3 g2(NPROJ*HIDDEN/128, (BSZ*SEQ)/128);   // (24, 64)
    qkv_gemm_f16<<<g2, 256, 2*2*SABH*2>>>(bq, bk, bv);

    dim3 g3(SEQ/64, BH);                         // (32, 64)
    attn_f16<<<g3, 128, ATTN_SMEM>>>(mask, out);
}

// round 8
// speedup vs baseline: 2.1115x; 1.0038x over previous
#include <cuda_runtime.h>
#include <cuda_fp16.h>
#include <cstdint>

#define HIDDEN 1024
#define HEADS 16
#define HD 64
#define RANK 16
#define BSZ 4
#define SEQ 2048
#define BH (BSZ*HEADS)          // 64
#define NPROJ 3
#define LORA_SCALE (1.0f/16.0f)
#define SM_SCALE 0.125f          // 1/sqrt(64)

// PERM16: within 16-group, place k-slots (2t,2t+1,2t+8,2t+9) adjacent at 4t..4t+3
__device__ __host__ __forceinline__ int perm16(int r) {
    return (r < 8) ? (((r >> 1) << 2) | (r & 1))
                   : ((((r - 8) >> 1) << 2) + 2 + (r & 1));
}
#define PERM16F(k) (((k) & ~15) | perm16((k) & 15))

// Scratch (no allocations allowed)
__device__ __half g_Wh  [(size_t)NPROJ*HIDDEN*HIDDEN];  // fp16, k-perm16
__device__ __half g_Xh  [(size_t)BSZ*SEQ*HIDDEN];       // fp16, k-perm16
__device__ __half g_QKVh[(size_t)NPROJ*BH*SEQ*HD];      // Q,K: [bh][s][perm16 d]; V: [bh][d][perm16-block s]

// ---------------------------------------------------------------------------
__device__ __forceinline__ void mma_f16(float c[4], const unsigned a[4], unsigned b0, unsigned b1) {
    asm volatile(
        "mma.sync.aligned.m16n8k16.row.col.f32.f16.f16.f32 "
        "{%0,%1,%2,%3},{%4,%5,%6,%7},{%8,%9},{%0,%1,%2,%3};"
        : "+f"(c[0]), "+f"(c[1]), "+f"(c[2]), "+f"(c[3])
        : "r"(a[0]), "r"(a[1]), "r"(a[2]), "r"(a[3]), "r"(b0), "r"(b1));
}
__device__ __forceinline__ unsigned pack2(float lo, float hi) {
    __half2 h = __floats2half2_rn(lo, hi);
    return *(unsigned*)&h;
}
__device__ __forceinline__ void cpa16(void* dst, const void* src) {
    unsigned a = (unsigned)__cvta_generic_to_shared(dst);
    asm volatile("cp.async.cg.shared.global [%0], [%1], 16;" :: "r"(a), "l"(src));
}
#define CP_COMMIT asm volatile("cp.async.commit_group;")
#define CP_WAIT0  asm volatile("cp.async.wait_group 0;")
#define CP_WAIT1  asm volatile("cp.async.wait_group 1;")

// ---------------------------------------------------------------------------
// Kernel 1a: W_eff = fp16(W + (1/16) B A), k-perm16, 4 elems/thread
// ---------------------------------------------------------------------------
__global__ void weff_kernel(const float* __restrict__ Wq, const float* __restrict__ Aq, const float* __restrict__ Bq,
                            const float* __restrict__ Wk, const float* __restrict__ Ak, const float* __restrict__ Bk,
                            const float* __restrict__ Wv, const float* __restrict__ Av, const float* __restrict__ Bv) {
    int idx = blockIdx.x * blockDim.x + threadIdx.x;      // over NPROJ*2^18 float4s
    if (idx >= NPROJ*HIDDEN*HIDDEN/4) return;
    int p   = idx >> 18;
    int nk4 = idx & ((1 << 18) - 1);
    int n   = nk4 >> 8;
    int k   = (nk4 & 255) << 2;
    const float* W = (p == 0) ? Wq : ((p == 1) ? Wk : Wv);
    const float* A = (p == 0) ? Aq : ((p == 1) ? Ak : Av);
    const float* B = (p == 0) ? Bq : ((p == 1) ? Bk : Bv);
    float4 acc = make_float4(0.f, 0.f, 0.f, 0.f);
#pragma unroll
    for (int r = 0; r < RANK; r++) {
        float br = B[n*RANK + r];
        float4 a = *(const float4*)&A[r*HIDDEN + k];
        acc.x += br*a.x; acc.y += br*a.y; acc.z += br*a.z; acc.w += br*a.w;
    }
    float4 w = *(const float4*)&W[n*HIDDEN + k];
    __half* dst = g_Wh + ((size_t)p << 20) + ((size_t)n << 10) + (k & ~15);
    int r0 = k & 15;       // 0,4,8,12
    *(__half2*)&dst[perm16(r0)]     = __floats2half2_rn(w.x + LORA_SCALE*acc.x, w.y + LORA_SCALE*acc.y);
    *(__half2*)&dst[perm16(r0 + 2)] = __floats2half2_rn(w.z + LORA_SCALE*acc.z, w.w + LORA_SCALE*acc.w);
}

// ---------------------------------------------------------------------------
// Kernel 1b: X -> fp16, k-perm16
// ---------------------------------------------------------------------------
__global__ void xh_kernel(const float* __restrict__ X) {
    int i = blockIdx.x * blockDim.x + threadIdx.x;   // float4 index
    int base = i << 2;
    float4 v = ((const float4*)X)[i];
    __half* dst = g_Xh + (size_t)(base & ~15);
    int r = base & 15;       // 0,4,8,12
    *(__half2*)&dst[perm16(r)]     = __floats2half2_rn(v.x, v.y);
    *(__half2*)&dst[perm16(r + 2)] = __floats2half2_rn(v.z, v.w);
}

// ---------------------------------------------------------------------------
// Kernel 2: QKV GEMM, mma fp16 m16n8k16, cp.async 2-stage, K-slab 64.
// ---------------------------------------------------------------------------
#define GST 80                 // smem stride (halves)
#define SABH (128*GST)         // halves per matrix per buffer

__global__ __launch_bounds__(256, 2) void qkv_gemm_f16(const float* __restrict__ bq,
                                                       const float* __restrict__ bk,
                                                       const float* __restrict__ bv) {
    extern __shared__ __align__(16) __half gsm[];
    int tid  = threadIdx.x;
    int lane = tid & 31;
    int wid  = tid >> 5;
    int wm   = wid & 3;
    int wn   = wid >> 2;
    int g    = lane >> 2;
    int tig  = lane & 3;
    int m0 = blockIdx.y * 128;
    int n0 = blockIdx.x * 128;

    float acc[2][8][4];
#pragma unroll
    for (int mt = 0; mt < 2; mt++)
#pragma unroll
        for (int nt = 0; nt < 8; nt++)
#pragma unroll
            for (int i = 0; i < 4; i++) acc[mt][nt][i] = 0.f;

#define ISSUE(slab, buf) do {                                                      \
        __half* sA_ = gsm + (buf)*2*SABH;                                          \
        __half* sB_ = sA_ + SABH;                                                  \
        int kc_ = (slab)*64;                                                       \
        _Pragma("unroll")                                                          \
        for (int it = 0; it < 4; it++) {                                           \
            int f   = tid + it * 256;          /* 1024 chunks of 8 halves */       \
            int row = f >> 3;                                                      \
            int ch  = (f & 7) << 3;                                                \
            cpa16(sA_ + row*GST + ch, g_Xh + (size_t)(m0+row)*HIDDEN + kc_ + ch);  \
            cpa16(sB_ + row*GST + ch, g_Wh + (size_t)(n0+row)*HIDDEN + kc_ + ch);  \
        }                                                                          \
        CP_COMMIT;                                                                 \
    } while (0)

    ISSUE(0, 0);

    for (int s = 0; s < HIDDEN/64; s++) {
        if (s + 1 < HIDDEN/64) { ISSUE(s+1, (s+1)&1); CP_WAIT1; }
        else                   { CP_WAIT0; }
        __syncthreads();

        const __half* hA = gsm + (s&1)*2*SABH;
        const __half* hB = hA + SABH;
#pragma unroll
        for (int ks = 0; ks < 4; ks++) {
            int ko = ks*16 + 4*tig;
            unsigned a[2][4], b[8][2];
#pragma unroll
            for (int mt = 0; mt < 2; mt++) {
                int rb = wm*32 + mt*16;
                uint2 lo = *(const uint2*)&hA[(rb+g  )*GST + ko];
                uint2 hi = *(const uint2*)&hA[(rb+g+8)*GST + ko];
                a[mt][0] = lo.x; a[mt][1] = hi.x;
                a[mt][2] = lo.y; a[mt][3] = hi.y;
            }
#pragma unroll
            for (int nt = 0; nt < 8; nt++) {
                int cb = wn*64 + nt*8;
                uint2 bb = *(const uint2*)&hB[(cb+g)*GST + ko];
                b[nt][0] = bb.x; b[nt][1] = bb.y;
            }
#pragma unroll
            for (int mt = 0; mt < 2; mt++)
#pragma unroll
                for (int nt = 0; nt < 8; nt++)
                    mma_f16(acc[mt][nt], a[mt], b[nt][0], b[nt][1]);
        }
        __syncthreads();
    }

    // epilogue: bias + fp16 round; Q,K -> [bh][s][perm16 d]; V -> [bh][d][perm16-block s]
#pragma unroll
    for (int mt = 0; mt < 2; mt++) {
#pragma unroll
        for (int half = 0; half < 2; half++) {
            int m  = m0 + wm*32 + mt*16 + g + half*8;
            int b  = m >> 11;
            int sq = m & 2047;
            int sp = (sq & ~15) | perm16(sq & 15);
#pragma unroll
            for (int nt = 0; nt < 8; nt++) {
                int n  = n0 + wn*64 + nt*8 + 2*tig;
                int p  = n >> 10;
                int hn = n & 1023;
                int h  = hn >> 6;
                int d  = n & 63;
                const float* bias = (p == 0) ? bq : ((p == 1) ? bk : bv);
                float v0 = acc[mt][nt][half*2 + 0] + bias[hn];
                float v1 = acc[mt][nt][half*2 + 1] + bias[hn + 1];
                int bh = b*HEADS + h;
                if (p < 2) {
                    __half* dst = &g_QKVh[(((size_t)p * BH + bh) * SEQ + sq) * HD + PERM16F(d)];
                    *(__half2*)dst = __floats2half2_rn(v0, v1);
                } else {
                    __half* dst = &g_QKVh[(size_t)2*BH*SEQ*HD + ((size_t)bh*HD + d) * SEQ + sp];
                    dst[0]   = __float2half_rn(v0);
                    dst[SEQ] = __float2half_rn(v1);
                }
            }
        }
    }
}

// ---------------------------------------------------------------------------
// Kernel 3: flash attention, mma fp16, Q-tile 128 / 256 threads (8 warps).
// P stays in registers; K/V double-buffered cp.async one tile ahead.
// ---------------------------------------------------------------------------
#define QB 128
#define SKH 80                       // halves stride
#define KVBH (2*64*SKH)              // halves per buffer (K 64 rows + V 64 rows)
#define ATTN_SMEM (2*KVBH*2 + 2*64*4)   // bytes

__global__ __launch_bounds__(256, 2) void attn_f16(const float* __restrict__ mask,
                                                   float* __restrict__ out) {
    extern __shared__ __align__(16) char smem_[];
    __half* sKV = (__half*)smem_;                    // [2][K 64*SKH | V 64*SKH]
    float*  sMb = (float*)(smem_ + 2*KVBH*2);        // [2][64]

    int bh = blockIdx.y;
    int b  = bh >> 4;
    int h  = bh & 15;
    int q0 = blockIdx.x * QB;
    int tid  = threadIdx.x;
    int w    = tid >> 5;             // 0..7
    int lane = tid & 31;
    int g    = lane >> 2;
    int tig  = lane & 3;

    const float* maskb = mask + b * SEQ;
    const __half* Kg0 = g_QKVh + ((size_t)(BH + bh) * SEQ) * HD;
    const __half* Vg0 = g_QKVh + (size_t)2*BH*SEQ*HD + (size_t)bh * HD * SEQ;

    // ---- stage Q (128 rows x 64 halves, perm16 d) into buf0 region (exactly KVBH) ----
    {
        const __half* Qg = g_QKVh + ((size_t)bh * SEQ + q0) * HD;
#pragma unroll
        for (int it = 0; it < 4; it++) {
            int f   = tid + it * 256;       // 1024 chunks
            int row = f >> 3;
            int ch  = (f & 7) << 3;
            cpa16(sKV + row*SKH + ch, Qg + row*HD + ch);
        }
        CP_COMMIT; CP_WAIT0;
    }
    __syncthreads();

    unsigned qa[4][4];
    int qb = w * 16;
#pragma unroll
    for (int ks = 0; ks < 4; ks++) {
        int ko = ks*16 + 4*tig;
        uint2 lo = *(const uint2*)&sKV[(qb+g  )*SKH + ko];
        uint2 hi = *(const uint2*)&sKV[(qb+g+8)*SKH + ko];
        qa[ks][0] = lo.x; qa[ks][1] = hi.x;
        qa[ks][2] = lo.y; qa[ks][3] = hi.y;
    }
    __syncthreads();   // buf0 reusable

    float o[8][4];
#pragma unroll
    for (int nt = 0; nt < 8; nt++)
#pragma unroll
        for (int i = 0; i < 4; i++) o[nt][i] = 0.f;
    float mlo = -1e30f, mhi = -1e30f, llo = 0.f, lhi = 0.f;

#define AISSUE(ti, bf) do {                                                        \
        __half* sK_ = sKV + (bf)*KVBH;                                             \
        __half* sV_ = sK_ + 64*SKH;                                                \
        int kt_ = (ti)*64;                                                         \
        _Pragma("unroll")                                                          \
        for (int it = 0; it < 2; it++) {                                           \
            int f   = tid + it * 256;          /* 512 chunks each */               \
            int row = f >> 3;                                                      \
            int ch  = (f & 7) << 3;                                                \
            cpa16(sK_ + row*SKH + ch, Kg0 + (size_t)(kt_ + row)*HD + ch);          \
            cpa16(sV_ + row*SKH + ch, Vg0 + (size_t)row*SEQ + kt_ + ch);           \
        }                                                                          \
        if (tid < 16) cpa16(sMb + (bf)*64 + tid*4, maskb + kt_ + tid*4);           \
        CP_COMMIT;                                                                 \
    } while (0)

    AISSUE(0, 0);

    for (int ti = 0; ti < SEQ/64; ti++) {
        int bf = ti & 1;
        if (ti + 1 < SEQ/64) { AISSUE(ti+1, bf^1); CP_WAIT1; }
        else                 { CP_WAIT0; }
        __syncthreads();

        const __half* uK = sKV + bf*KVBH;
        const __half* uV = uK + 64*SKH;
        const float*  sM = sMb + bf*64;

        // ---- S = Q K^T ----
        float s[8][4];
#pragma unroll
        for (int nt = 0; nt < 8; nt++) {
            s[nt][0] = s[nt][1] = s[nt][2] = s[nt][3] = 0.f;
#pragma unroll
            for (int ks = 0; ks < 4; ks++) {
                uint2 bb = *(const uint2*)&uK[(nt*8+g)*SKH + ks*16 + 4*tig];
                mma_f16(s[nt], qa[ks], bb.x, bb.y);
            }
        }

        // ---- scale + mask + tile max ----
        float tml = -1e30f, tmh = -1e30f;
#pragma unroll
        for (int nt = 0; nt < 8; nt++) {
            int c = nt*8 + 2*tig;
            float m0v = sM[c], m1v = sM[c+1];
            s[nt][0] = s[nt][0] * SM_SCALE + m0v;
            s[nt][1] = s[nt][1] * SM_SCALE + m1v;
            s[nt][2] = s[nt][2] * SM_SCALE + m0v;
            s[nt][3] = s[nt][3] * SM_SCALE + m1v;
            tml = fmaxf(tml, fmaxf(s[nt][0], s[nt][1]));
            tmh = fmaxf(tmh, fmaxf(s[nt][2], s[nt][3]));
        }
        tml = fmaxf(tml, __shfl_xor_sync(0xffffffff, tml, 1));
        tml = fmaxf(tml, __shfl_xor_sync(0xffffffff, tml, 2));
        tmh = fmaxf(tmh, __shfl_xor_sync(0xffffffff, tmh, 1));
        tmh = fmaxf(tmh, __shfl_xor_sync(0xffffffff, tmh, 2));

        float mnl = fmaxf(mlo, tml), mnh = fmaxf(mhi, tmh);
        float cl = __expf(mlo - mnl), ch = __expf(mhi - mnh);
        llo *= cl; lhi *= ch;
        mlo = mnl; mhi = mnh;
#pragma unroll
        for (int nt = 0; nt < 8; nt++) {
            o[nt][0] *= cl; o[nt][1] *= cl;
            o[nt][2] *= ch; o[nt][3] *= ch;
        }

        // ---- exp in place + sums ----
#pragma unroll
        for (int nt = 0; nt < 8; nt++) {
            s[nt][0] = __expf(s[nt][0] - mnl);
            s[nt][1] = __expf(s[nt][1] - mnl);
            s[nt][2] = __expf(s[nt][2] - mnh);
            s[nt][3] = __expf(s[nt][3] - mnh);
            llo += s[nt][0] + s[nt][1];
            lhi += s[nt][2] + s[nt][3];
        }
        unsigned pa[4][4];
#pragma unroll
        for (int j = 0; j < 4; j++) {
            pa[j][0] = pack2(s[2*j  ][0], s[2*j  ][1]);
            pa[j][1] = pack2(s[2*j  ][2], s[2*j  ][3]);
            pa[j][2] = pack2(s[2*j+1][0], s[2*j+1][1]);
            pa[j][3] = pack2(s[2*j+1][2], s[2*j+1][3]);
        }

        // ---- O += P V ----
#pragma unroll
        for (int nt = 0; nt < 8; nt++) {
#pragma unroll
            for (int j = 0; j < 4; j++) {
                uint2 bb = *(const uint2*)&uV[(nt*8+g)*SKH + j*16 + 4*tig];
                mma_f16(o[nt], pa[j], bb.x, bb.y);
            }
        }
        __syncthreads();
    }

    // ---- finalize ----
    llo += __shfl_xor_sync(0xffffffff, llo, 1);
    llo += __shfl_xor_sync(0xffffffff, llo, 2);
    lhi += __shfl_xor_sync(0xffffffff, lhi, 1);
    lhi += __shfl_xor_sync(0xffffffff, lhi, 2);
    float invl = 1.f / llo, invh = 1.f / lhi;

    int row_lo = q0 + qb + g;
    int row_hi = row_lo + 8;
    float* out_lo = out + ((size_t)(b * SEQ + row_lo)) * HIDDEN + h * HD;
    float* out_hi = out + ((size_t)(b * SEQ + row_hi)) * HIDDEN + h * HD;
#pragma unroll
    for (int nt = 0; nt < 8; nt++) {
        int d = nt*8 + 2*tig;
        *(float2*)(out_lo + d) = make_float2(o[nt][0] * invl, o[nt][1] * invl);
        *(float2*)(out_hi + d) = make_float2(o[nt][2] * invh, o[nt][3] * invh);
    }
}

// ---------------------------------------------------------------------------
extern "C" void kernel_launch(void* const* d_in, const int* in_sizes, int n_in,
                              void* d_out, int out_size) {
    const float* X    = (const float*)d_in[0];
    const float* mask = (const float*)d_in[1];
    const float* Wq = (const float*)d_in[2];  const float* bq = (const float*)d_in[3];
    const float* Aq = (const float*)d_in[4];  const float* Bq = (const float*)d_in[5];
    const float* Wk = (const float*)d_in[6];  const float* bk = (const float*)d_in[7];
    const float* Ak = (const float*)d_in[8];  const float* Bk = (const float*)d_in[9];
    const float* Wv = (const float*)d_in[10]; const float* bv = (const float*)d_in[11];
    const float* Av = (const float*)d_in[12]; const float* Bv = (const float*)d_in[13];
    float* out = (float*)d_out;

    weff_kernel<<<(NPROJ*HIDDEN*HIDDEN/4)/256, 256>>>(Wq, Aq, Bq, Wk, Ak, Bk, Wv, Av, Bv);
    xh_kernel<<<(BSZ*SEQ*HIDDEN/4)/256, 256>>>(X);

    static bool attr_done = false;
    if (!attr_done) {
        cudaFuncSetAttribute(qkv_gemm_f16, cudaFuncAttributeMaxDynamicSharedMemorySize, 2*2*SABH*2);
        cudaFuncSetAttribute(attn_f16,     cudaFuncAttributeMaxDynamicSharedMemorySize, ATTN_SMEM);
        attr_done = true;
    }

    dim3 g2(NPROJ*HIDDEN/128, (BSZ*SEQ)/128);   // (24, 64)
    qkv_gemm_f16<<<g2, 256, 2*2*SABH*2>>>(bq, bk, bv);

    dim3 g3(SEQ/QB, BH);                         // (16, 64)
    attn_f16<<<g3, 256, ATTN_SMEM>>>(mask, out);
}